// round 2
// baseline (speedup 1.0000x reference)
#include <cuda_runtime.h>
#include <math.h>

// Shape fixed by reference: [4,1,128,256,256] fp32
#define IMG_W    256
#define IMG_H    256
#define NSLICES  512                 // B*D
#define STRIP_H  64                  // rows per block
#define STRIPS   (IMG_H / STRIP_H)   // 4
#define NB       (NSLICES * STRIPS)  // 2048 blocks
#define YT       4                   // y-threads per block
#define NR       (STRIP_H / YT)      // 16 output rows per thread
#define N_TOTAL  (4.0 * 128.0 * 256.0 * 256.0)

__device__ float        g_partials[NB];
__device__ unsigned int g_count = 0;

// Load 6 horizontally-contiguous values n[0..5] covering cols [cb-1, cb+4]
// of `row` (zero outside image). One LDG.128 + warp shuffles; lanes 0/31
// patch the cross-warp boundary with a predicated scalar LDG.
__device__ __forceinline__ void load_row6(const float* __restrict__ img,
                                          int row, int cb, int lane,
                                          bool row_ok, float n[6])
{
    float4 v = make_float4(0.f, 0.f, 0.f, 0.f);
    if (row_ok)
        v = __ldg(reinterpret_cast<const float4*>(img + row * IMG_W + cb));

    float lft = __shfl_up_sync(0xffffffffu, v.w, 1);
    float rgt = __shfl_down_sync(0xffffffffu, v.x, 1);

    if (row_ok) {
        if (lane == 0)
            lft = (cb == 0) ? 0.f : __ldg(img + row * IMG_W + cb - 1);
        if (lane == 31)
            rgt = (cb + 4 >= IMG_W) ? 0.f : __ldg(img + row * IMG_W + cb + 4);
    } else {
        lft = 0.f; rgt = 0.f;
    }
    n[0] = lft; n[1] = v.x; n[2] = v.y; n[3] = v.z; n[4] = v.w; n[5] = rgt;
}

// Separable row aggregates for 4 columns:
//   h1 = r - l  (feeds ex = h1[y-1] + 2h1[y] + h1[y+1])
//   h2 = l + 2m + r  (feeds ey = h2[y+1] - h2[y-1])
__device__ __forceinline__ void row_agg(const float n[6], float h1[4], float h2[4])
{
    #pragma unroll
    for (int j = 0; j < 4; j++) {
        h1[j] = n[j + 2] - n[j];
        h2[j] = fmaf(2.f, n[j + 1], n[j] + n[j + 2]);
    }
}

__global__ __launch_bounds__(256)
void edge_loss_kernel(const float* __restrict__ pred,
                      const float* __restrict__ target,
                      float* __restrict__ out)
{
    __shared__ float warp_sums[8];
    __shared__ int   s_last;

    const int tid   = threadIdx.x;
    const int x     = tid & 63;          // 0..63 -> cols [4x, 4x+3]
    const int ty    = tid >> 6;          // 0..3
    const int lane  = tid & 31;
    const int cb    = x << 2;
    const int strip = blockIdx.x;        // 0..3
    const int slice = blockIdx.y;        // 0..511
    const int r0    = strip * STRIP_H + ty * NR;

    const size_t base = (size_t)slice * (IMG_H * IMG_W);
    const float* __restrict__ P = pred + base;
    const float* __restrict__ T = target + base;

    float n[6];
    float ph1p[4], ph2p[4], ph1c[4], ph2c[4];
    float th1p[4], th2p[4], th1c[4], th2c[4];

    // Prologue: rows r0-1 (prev) and r0 (cur)
    load_row6(P, r0 - 1, cb, lane, r0 - 1 >= 0, n); row_agg(n, ph1p, ph2p);
    load_row6(T, r0 - 1, cb, lane, r0 - 1 >= 0, n); row_agg(n, th1p, th2p);
    load_row6(P, r0,     cb, lane, true,        n); row_agg(n, ph1c, ph2c);
    load_row6(T, r0,     cb, lane, true,        n); row_agg(n, th1c, th2c);

    float acc = 0.f;

    #pragma unroll
    for (int i = 0; i < NR; i++) {
        const int  row    = r0 + 1 + i;           // new bottom row
        const bool row_ok = (row < IMG_H);

        float ph1n[4], ph2n[4], th1n[4], th2n[4];
        load_row6(P, row, cb, lane, row_ok, n); row_agg(n, ph1n, ph2n);
        load_row6(T, row, cb, lane, row_ok, n); row_agg(n, th1n, th2n);

        #pragma unroll
        for (int j = 0; j < 4; j++) {
            float ex = fmaf(2.f, ph1c[j], ph1p[j]) + ph1n[j];
            float ey = ph2n[j] - ph2p[j];
            const float magp = sqrtf(fmaf(ex, ex, fmaf(ey, ey, 1e-8f)));

            ex = fmaf(2.f, th1c[j], th1p[j]) + th1n[j];
            ey = th2n[j] - th2p[j];
            const float magt = sqrtf(fmaf(ex, ex, fmaf(ey, ey, 1e-8f)));

            acc += fabsf(magp - magt);
        }

        #pragma unroll
        for (int j = 0; j < 4; j++) {
            ph1p[j] = ph1c[j]; ph1c[j] = ph1n[j];
            ph2p[j] = ph2c[j]; ph2c[j] = ph2n[j];
            th1p[j] = th1c[j]; th1c[j] = th1n[j];
            th2p[j] = th2c[j]; th2c[j] = th2n[j];
        }
    }

    // ---- Deterministic block reduction ----
    #pragma unroll
    for (int off = 16; off > 0; off >>= 1)
        acc += __shfl_down_sync(0xffffffffu, acc, off);
    if (lane == 0) warp_sums[tid >> 5] = acc;
    __syncthreads();

    if (tid == 0) {
        float s = 0.f;
        #pragma unroll
        for (int i = 0; i < 8; i++) s += warp_sums[i];
        g_partials[blockIdx.y * gridDim.x + blockIdx.x] = s;
        __threadfence();
        const unsigned old = atomicAdd(&g_count, 1u);
        s_last = (old == NB - 1) ? 1 : 0;
    }
    __syncthreads();

    // ---- Last block: deterministic final reduce (fixed order, double) ----
    if (s_last) {
        __shared__ double dred[256];
        double s = 0.0;
        #pragma unroll 8
        for (int i = tid; i < NB; i += 256)
            s += (double)g_partials[i];
        dred[tid] = s;
        __syncthreads();
        #pragma unroll
        for (int off = 128; off > 0; off >>= 1) {
            if (tid < off) dred[tid] += dred[tid + off];
            __syncthreads();
        }
        if (tid == 0) {
            out[0]  = (float)(dred[0] / N_TOTAL);
            g_count = 0;   // reset for next graph replay
        }
    }
}

extern "C" void kernel_launch(void* const* d_in, const int* in_sizes, int n_in,
                              void* d_out, int out_size)
{
    (void)in_sizes; (void)n_in; (void)out_size;
    const float* pred   = (const float*)d_in[0];
    const float* target = (const float*)d_in[1];
    float* out = (float*)d_out;

    dim3 grid(STRIPS, NSLICES);   // 4 x 512 = 2048 blocks
    edge_loss_kernel<<<grid, 256>>>(pred, target, out);
}

// round 5
// speedup vs baseline: 1.9506x; 1.9506x over previous
#include <cuda_runtime.h>
#include <math.h>

// Shape fixed by reference: [4,1,128,256,256] fp32
#define IMG_W    256
#define IMG_H    256
#define NSLICES  512                 // B*D
#define STRIP_H  64                  // rows per block
#define STRIPS   (IMG_H / STRIP_H)   // 4
#define NB       (NSLICES * STRIPS)  // 2048 blocks
#define YT       4                   // y-thread groups per block
#define NR       (STRIP_H / YT)      // 16 output rows per thread
#define N_TOTAL  (4.0 * 128.0 * 256.0 * 256.0)

__device__ float        g_partials[NB];
__device__ unsigned int g_count = 0;

struct Row6 { float n0, n1, n2, n3, n4, n5; };

// Raw loads only — no math. One aligned float4 + two independent halo
// scalars (L1 hits: same 128B lines as neighboring lanes' vectors).
// No shuffles, no convergence points, nothing between the LDGs.
__device__ __forceinline__ Row6 load_row(const float* __restrict__ img,
                                         int row, int cb,
                                         bool row_ok, bool has_l, bool has_r)
{
    Row6 o;
    float4 v = make_float4(0.f, 0.f, 0.f, 0.f);
    float  l = 0.f, r = 0.f;
    if (row_ok) {
        const float* p = img + row * IMG_W + cb;
        v = *reinterpret_cast<const float4*>(p);
        if (has_l) l = p[-1];
        if (has_r) r = p[4];
    }
    o.n0 = l; o.n1 = v.x; o.n2 = v.y; o.n3 = v.z; o.n4 = v.w; o.n5 = r;
    return o;
}

// Separable row aggregates for 4 columns from 6 horizontal values:
//   h1 = r - l        (ex = h1[y-1] + 2h1[y] + h1[y+1])
//   h2 = l + 2m + r   (ey = h2[y+1] - h2[y-1])
__device__ __forceinline__ void row_agg(const Row6& n, float h1[4], float h2[4])
{
    h1[0] = n.n2 - n.n0;  h2[0] = fmaf(2.f, n.n1, n.n0 + n.n2);
    h1[1] = n.n3 - n.n1;  h2[1] = fmaf(2.f, n.n2, n.n1 + n.n3);
    h1[2] = n.n4 - n.n2;  h2[2] = fmaf(2.f, n.n3, n.n2 + n.n4);
    h1[3] = n.n5 - n.n3;  h2[3] = fmaf(2.f, n.n4, n.n3 + n.n5);
}

__global__ __launch_bounds__(256)
void edge_loss_kernel(const float* __restrict__ pred,
                      const float* __restrict__ target,
                      float* __restrict__ out)
{
    __shared__ float warp_sums[8];
    __shared__ int   s_last;

    const int tid  = threadIdx.x;
    const int x    = tid & 63;            // 0..63 -> cols [4x, 4x+3]
    const int ty   = tid >> 6;            // 0..3
    const int lane = tid & 31;
    const int cb   = x << 2;
    const bool has_l = (x != 0);
    const bool has_r = (x != 63);

    const int r0 = blockIdx.x * STRIP_H + ty * NR;

    const size_t base = (size_t)blockIdx.y * (IMG_H * IMG_W);
    const float* __restrict__ P = pred + base;
    const float* __restrict__ T = target + base;

    float ph1p[4], ph2p[4], ph1c[4], ph2c[4];
    float th1p[4], th2p[4], th1c[4], th2c[4];

    // Prologue: rows r0-1 (prev) and r0 (cur). Issue all 4 row-loads
    // before any aggregate math.
    {
        Row6 pp = load_row(P, r0 - 1, cb, r0 > 0, has_l, has_r);
        Row6 tp = load_row(T, r0 - 1, cb, r0 > 0, has_l, has_r);
        Row6 pc = load_row(P, r0,     cb, true,   has_l, has_r);
        Row6 tc = load_row(T, r0,     cb, true,   has_l, has_r);
        row_agg(pp, ph1p, ph2p);
        row_agg(tp, th1p, th2p);
        row_agg(pc, ph1c, ph2c);
        row_agg(tc, th1c, th2c);
    }

    float acc = 0.f;

    #pragma unroll
    for (int i = 0; i < NR; i++) {
        const int  row    = r0 + 1 + i;          // new bottom row
        const bool row_ok = (row < IMG_H);

        // Phase 1: all 12 raw LDGs for this row, back-to-back.
        const Row6 pn = load_row(P, row, cb, row_ok, has_l, has_r);
        const Row6 tn = load_row(T, row, cb, row_ok, has_l, has_r);

        // Phase 2: aggregates + Sobel magnitude.
        float ph1n[4], ph2n[4], th1n[4], th2n[4];
        row_agg(pn, ph1n, ph2n);
        row_agg(tn, th1n, th2n);

        #pragma unroll
        for (int j = 0; j < 4; j++) {
            float ex = fmaf(2.f, ph1c[j], ph1p[j]) + ph1n[j];
            float ey = ph2n[j] - ph2p[j];
            float s  = fmaf(ex, ex, fmaf(ey, ey, 1e-8f));
            const float magp = s * rsqrtf(s);     // sqrt via MUFU.RSQ + mul

            ex = fmaf(2.f, th1c[j], th1p[j]) + th1n[j];
            ey = th2n[j] - th2p[j];
            s  = fmaf(ex, ex, fmaf(ey, ey, 1e-8f));
            const float magt = s * rsqrtf(s);

            acc += fabsf(magp - magt);
        }

        #pragma unroll
        for (int j = 0; j < 4; j++) {
            ph1p[j] = ph1c[j]; ph1c[j] = ph1n[j];
            ph2p[j] = ph2c[j]; ph2c[j] = ph2n[j];
            th1p[j] = th1c[j]; th1c[j] = th1n[j];
            th2p[j] = th2c[j]; th2c[j] = th2n[j];
        }
    }

    // ---- Deterministic block reduction ----
    #pragma unroll
    for (int off = 16; off > 0; off >>= 1)
        acc += __shfl_down_sync(0xffffffffu, acc, off);
    if (lane == 0) warp_sums[tid >> 5] = acc;
    __syncthreads();

    if (tid == 0) {
        float s = 0.f;
        #pragma unroll
        for (int i = 0; i < 8; i++) s += warp_sums[i];
        g_partials[blockIdx.y * gridDim.x + blockIdx.x] = s;
        __threadfence();
        const unsigned old = atomicAdd(&g_count, 1u);
        s_last = (old == NB - 1) ? 1 : 0;
    }
    __syncthreads();

    // ---- Last block: deterministic final reduce (fixed order, double) ----
    if (s_last) {
        __shared__ double dred[256];
        double s = 0.0;
        #pragma unroll 8
        for (int i = tid; i < NB; i += 256)
            s += (double)g_partials[i];
        dred[tid] = s;
        __syncthreads();
        #pragma unroll
        for (int off = 128; off > 0; off >>= 1) {
            if (tid < off) dred[tid] += dred[tid + off];
            __syncthreads();
        }
        if (tid == 0) {
            out[0]  = (float)(dred[0] / N_TOTAL);
            g_count = 0;   // reset for next graph replay
        }
    }
}

extern "C" void kernel_launch(void* const* d_in, const int* in_sizes, int n_in,
                              void* d_out, int out_size)
{
    (void)in_sizes; (void)n_in; (void)out_size;
    const float* pred   = (const float*)d_in[0];
    const float* target = (const float*)d_in[1];
    float* out = (float*)d_out;

    dim3 grid(STRIPS, NSLICES);   // 4 x 512 = 2048 blocks
    edge_loss_kernel<<<grid, 256>>>(pred, target, out);
}